// round 1
// baseline (speedup 1.0000x reference)
#include <cuda_runtime.h>
#include <math_constants.h>

#define T_SRC   4096
#define T_DST   4096
#define HID     128
#define NHEADS  8
#define KTOP    128
#define TDENSE  1024
#define NTHREADS 256
#define NWARPS  (NTHREADS / 32)

// Map float to uint32 key with the same total order (all finite values).
__device__ __forceinline__ unsigned fkey(float f) {
    unsigned b = __float_as_uint(f);
    return b ^ ((b & 0x80000000u) ? 0xFFFFFFFFu : 0x80000000u);
}

__device__ __forceinline__ float block_max(float v, float* sred) {
    #pragma unroll
    for (int o = 16; o; o >>= 1) v = fmaxf(v, __shfl_xor_sync(0xFFFFFFFFu, v, o));
    if ((threadIdx.x & 31) == 0) sred[threadIdx.x >> 5] = v;
    __syncthreads();
    if (threadIdx.x < 32) {
        float x = (threadIdx.x < NWARPS) ? sred[threadIdx.x] : -CUDART_INF_F;
        #pragma unroll
        for (int o = 4; o; o >>= 1) x = fmaxf(x, __shfl_xor_sync(0xFFFFFFFFu, x, o));
        if (threadIdx.x == 0) sred[0] = x;
    }
    __syncthreads();
    v = sred[0];
    __syncthreads();
    return v;
}

__device__ __forceinline__ float block_sum(float v, float* sred) {
    #pragma unroll
    for (int o = 16; o; o >>= 1) v += __shfl_xor_sync(0xFFFFFFFFu, v, o);
    if ((threadIdx.x & 31) == 0) sred[threadIdx.x >> 5] = v;
    __syncthreads();
    if (threadIdx.x < 32) {
        float x = (threadIdx.x < NWARPS) ? sred[threadIdx.x] : 0.0f;
        #pragma unroll
        for (int o = 4; o; o >>= 1) x += __shfl_xor_sync(0xFFFFFFFFu, x, o);
        if (threadIdx.x == 0) sred[0] = x;
    }
    __syncthreads();
    v = sred[0];
    __syncthreads();
    return v;
}

__device__ __forceinline__ unsigned block_count(unsigned v, unsigned* sred) {
    #pragma unroll
    for (int o = 16; o; o >>= 1) v += __shfl_xor_sync(0xFFFFFFFFu, v, o);
    if ((threadIdx.x & 31) == 0) sred[threadIdx.x >> 5] = v;
    __syncthreads();
    if (threadIdx.x < 32) {
        unsigned x = (threadIdx.x < NWARPS) ? sred[threadIdx.x] : 0u;
        #pragma unroll
        for (int o = 4; o; o >>= 1) x += __shfl_xor_sync(0xFFFFFFFFu, x, o);
        if (threadIdx.x == 0) sred[0] = x;
    }
    __syncthreads();
    v = sred[0];
    __syncthreads();
    return v;
}

__global__ __launch_bounds__(NTHREADS)
void tree_attn_kernel(const float* __restrict__ q,
                      const float* __restrict__ k,
                      const float* __restrict__ v,
                      float* __restrict__ out) {
    const int qi = blockIdx.x;
    const int h  = blockIdx.y;
    const int tid = threadIdx.x;
    const int n = qi + 1;  // causal key count

    const float* qrow  = q + ((size_t)h * T_DST + qi) * HID;
    const float* kbase = k + (size_t)h * T_SRC * HID;
    const float* vbase = v + (size_t)h * T_SRC * HID;
    float*       orow  = out + ((size_t)h * T_DST + qi) * HID;

    __shared__ float s_scores[T_SRC];
    __shared__ float s_q[HID];
    __shared__ float s_redf[NWARPS];
    __shared__ unsigned s_redu[NWARPS];
    __shared__ float s_out[NTHREADS];
    __shared__ int   s_idx[KTOP];
    __shared__ float s_w[KTOP];
    __shared__ int   s_eq[KTOP];
    __shared__ unsigned s_ngt, s_neq;

    // load q row to shared
    for (int d = tid; d < HID; d += NTHREADS) s_q[d] = qrow[d];
    __syncthreads();

    // ---- scores: s_j = q . k_j for j in [0, n) ----
    for (int j = tid; j < n; j += NTHREADS) {
        const float4* kr = (const float4*)(kbase + (size_t)j * HID);
        float acc = 0.0f;
        #pragma unroll
        for (int d4 = 0; d4 < HID / 4; d4++) {
            float4 kk = kr[d4];
            const float4 qq = *(const float4*)(&s_q[d4 * 4]);
            acc = fmaf(kk.x, qq.x, acc);
            acc = fmaf(kk.y, qq.y, acc);
            acc = fmaf(kk.z, qq.z, acc);
            acc = fmaf(kk.w, qq.w, acc);
        }
        s_scores[j] = acc;
    }
    __syncthreads();

    // ---- row max ----
    float m = -CUDART_INF_F;
    for (int j = tid; j < n; j += NTHREADS) m = fmaxf(m, s_scores[j]);
    m = block_max(m, s_redf);

    if (qi < TDENSE) {
        // ================= dense causal softmax =================
        float psum = 0.0f;
        for (int j = tid; j < n; j += NTHREADS) {
            float e = __expf(s_scores[j] - m);
            s_scores[j] = e;
            psum += e;
        }
        float total = block_sum(psum, s_redf);
        float inv = 1.0f / total;

        const int d    = tid & (HID - 1);
        const int half = tid >> 7;  // 0 or 1
        float acc = 0.0f;
        for (int j = half; j < n; j += 2)
            acc = fmaf(s_scores[j], vbase[(size_t)j * HID + d], acc);
        s_out[tid] = acc;
        __syncthreads();
        if (tid < HID) orow[tid] = (s_out[tid] + s_out[tid + HID]) * inv;
    } else {
        // ================= sparse: exact top-128 =================
        // Binary search largest key u with count(key >= u) >= KTOP.
        unsigned long long lo = 0ull, hi = 0xFFFFFFFFull;
        while (lo < hi) {
            unsigned long long mid = (lo + hi + 1ull) >> 1;
            unsigned thr = (unsigned)mid;
            unsigned c = 0;
            for (int j = tid; j < n; j += NTHREADS)
                c += (fkey(s_scores[j]) >= thr) ? 1u : 0u;
            unsigned cnt = block_count(c, s_redu);
            if (cnt >= KTOP) lo = mid; else hi = mid - 1ull;
        }
        const unsigned t_key = (unsigned)lo;

        // Gather strictly-greater indices (order irrelevant) and ties.
        if (tid == 0) { s_ngt = 0u; s_neq = 0u; }
        __syncthreads();
        for (int j = tid; j < n; j += NTHREADS) {
            unsigned ky = fkey(s_scores[j]);
            if (ky > t_key) {
                unsigned p = atomicAdd(&s_ngt, 1u);
                s_idx[p] = j;
            } else if (ky == t_key) {
                unsigned p = atomicAdd(&s_neq, 1u);
                if (p < KTOP) s_eq[p] = j;
            }
        }
        __syncthreads();
        const int ngt = (int)s_ngt;
        const int neq = (int)s_neq;
        const int need = KTOP - ngt;  // 1 <= need <= neq

        if (need < neq && tid == 0) {
            // rare: select `need` smallest tie indices (match top_k tie order)
            int c = (neq < KTOP) ? neq : KTOP;
            for (int a = 0; a < need; a++) {
                int mb = a;
                for (int b = a + 1; b < c; b++)
                    if (s_eq[b] < s_eq[mb]) mb = b;
                int t2 = s_eq[a]; s_eq[a] = s_eq[mb]; s_eq[mb] = t2;
            }
        }
        __syncthreads();
        for (int a = tid; a < need; a += NTHREADS) s_idx[ngt + a] = s_eq[a];
        __syncthreads();

        // Softmax over the 128 selected scores (max m is in the set).
        float psum = 0.0f;
        for (int a = tid; a < KTOP; a += NTHREADS) {
            float e = __expf(s_scores[s_idx[a]] - m);
            s_w[a] = e;
            psum += e;
        }
        float total = block_sum(psum, s_redf);
        float inv = 1.0f / total;

        const int d    = tid & (HID - 1);
        const int half = tid >> 7;
        float acc = 0.0f;
        for (int a = half; a < KTOP; a += 2)
            acc = fmaf(s_w[a], vbase[(size_t)s_idx[a] * HID + d], acc);
        s_out[tid] = acc;
        __syncthreads();
        if (tid < HID) orow[tid] = (s_out[tid] + s_out[tid + HID]) * inv;
    }
}

extern "C" void kernel_launch(void* const* d_in, const int* in_sizes, int n_in,
                              void* d_out, int out_size) {
    const float* q = (const float*)d_in[0];
    const float* k = (const float*)d_in[1];
    const float* v = (const float*)d_in[2];
    float* out = (float*)d_out;
    dim3 grid(T_DST, NHEADS);
    tree_attn_kernel<<<grid, NTHREADS>>>(q, k, v, out);
}

// round 2
// speedup vs baseline: 3.7475x; 3.7475x over previous
#include <cuda_runtime.h>
#include <math_constants.h>

#define T_SRC   4096
#define T_DST   4096
#define HID     128
#define NHEADS  8
#define KTOP    128
#define TDENSE  1024
#define NT      256
#define QT      4
#define NW      (NT / 32)
#define NTILES  (T_DST / QT)

// Union region layout (bytes): hist[257] -> 1040 (padded), eq[128] -> 512, cnt[4] -> 16
#define UN_BYTES 1600
#define DYN_BYTES ((QT*T_SRC + QT*HID + QT*KTOP + QT*KTOP) * 4 + UN_BYTES)

// Order-preserving float -> uint32 key.
__device__ __forceinline__ unsigned fkey(float f) {
    unsigned b = __float_as_uint(f);
    return b ^ ((b & 0x80000000u) ? 0xFFFFFFFFu : 0x80000000u);
}

__device__ __forceinline__ float block_max(float v, float* sred) {
    #pragma unroll
    for (int o = 16; o; o >>= 1) v = fmaxf(v, __shfl_xor_sync(0xFFFFFFFFu, v, o));
    if ((threadIdx.x & 31) == 0) sred[threadIdx.x >> 5] = v;
    __syncthreads();
    if (threadIdx.x < 32) {
        float x = (threadIdx.x < NW) ? sred[threadIdx.x] : -CUDART_INF_F;
        #pragma unroll
        for (int o = 4; o; o >>= 1) x = fmaxf(x, __shfl_xor_sync(0xFFFFFFFFu, x, o));
        if (threadIdx.x == 0) sred[0] = x;
    }
    __syncthreads();
    v = sred[0];
    __syncthreads();
    return v;
}

__device__ __forceinline__ float block_sum(float v, float* sred) {
    #pragma unroll
    for (int o = 16; o; o >>= 1) v += __shfl_xor_sync(0xFFFFFFFFu, v, o);
    if ((threadIdx.x & 31) == 0) sred[threadIdx.x >> 5] = v;
    __syncthreads();
    if (threadIdx.x < 32) {
        float x = (threadIdx.x < NW) ? sred[threadIdx.x] : 0.0f;
        #pragma unroll
        for (int o = 4; o; o >>= 1) x += __shfl_xor_sync(0xFFFFFFFFu, x, o);
        if (threadIdx.x == 0) sred[0] = x;
    }
    __syncthreads();
    v = sred[0];
    __syncthreads();
    return v;
}

__global__ __launch_bounds__(NT, 3)
void tree_attn_tiled(const float* __restrict__ q,
                     const float* __restrict__ k,
                     const float* __restrict__ v,
                     float* __restrict__ out) {
    extern __shared__ char smem_raw[];
    float*    s_sc   = (float*)smem_raw;                 // [QT][T_SRC]
    float*    s_q    = s_sc + QT * T_SRC;                // [QT][HID]
    int*      s_idx  = (int*)(s_q + QT * HID);           // [QT][KTOP]
    float*    s_w    = (float*)(s_idx + QT * KTOP);      // [QT][KTOP]
    char*     s_un   = (char*)(s_w + QT * KTOP);         // union region
    float*    s_buf  = (float*)s_un;                     // [NT] (AV reduction phase)
    unsigned* s_hist = (unsigned*)s_un;                  // [257] (select phase)
    int*      s_eq   = (int*)(s_un + 1040);              // [128]
    unsigned* s_cnt  = (unsigned*)(s_un + 1040 + 512);   // [4]
    __shared__ float s_redf[NW];

    const int tile = (NTILES - 1) - blockIdx.x;  // longest rows first
    const int h    = blockIdx.y;
    const int tid  = threadIdx.x;
    const int qi0  = tile * QT;
    const int n_max = qi0 + QT;  // keys [0, n_max) cover all QT queries

    const float* kbase = k + (size_t)h * T_SRC * HID;
    const float* vbase = v + (size_t)h * T_SRC * HID;

    // load QT q rows (contiguous in memory)
    for (int d = tid; d < QT * HID; d += NT)
        s_q[d] = q[((size_t)h * T_DST + qi0) * HID + d];
    __syncthreads();

    // ---- scores for all QT queries, tracking per-query max ----
    float mx[QT];
    #pragma unroll
    for (int s = 0; s < QT; s++) mx[s] = -CUDART_INF_F;

    for (int j = tid; j < n_max; j += NT) {
        const float4* kr = (const float4*)(kbase + (size_t)j * HID);
        float acc[QT] = {0.f, 0.f, 0.f, 0.f};
        #pragma unroll 4
        for (int d4 = 0; d4 < HID / 4; d4++) {
            float4 kk = kr[d4];
            #pragma unroll
            for (int s = 0; s < QT; s++) {
                const float4 qq = *(const float4*)&s_q[s * HID + d4 * 4];
                acc[s] = fmaf(kk.x, qq.x, acc[s]);
                acc[s] = fmaf(kk.y, qq.y, acc[s]);
                acc[s] = fmaf(kk.z, qq.z, acc[s]);
                acc[s] = fmaf(kk.w, qq.w, acc[s]);
            }
        }
        #pragma unroll
        for (int s = 0; s < QT; s++) {
            bool ok = (j <= qi0 + s);
            s_sc[s * T_SRC + j] = ok ? acc[s] : -CUDART_INF_F;
            if (ok) mx[s] = fmaxf(mx[s], acc[s]);
        }
    }
    __syncthreads();

    float m[QT];
    #pragma unroll
    for (int s = 0; s < QT; s++) m[s] = block_max(mx[s], s_redf);

    float inv[QT];

    if (qi0 < TDENSE) {
        // ================= dense causal softmax =================
        float psum[QT] = {0.f, 0.f, 0.f, 0.f};
        for (int j = tid; j < n_max; j += NT) {
            #pragma unroll
            for (int s = 0; s < QT; s++) {
                float sc = s_sc[s * T_SRC + j];
                float e = (j <= qi0 + s) ? __expf(sc - m[s]) : 0.0f;
                s_sc[s * T_SRC + j] = e;
                psum[s] += e;
            }
        }
        #pragma unroll
        for (int s = 0; s < QT; s++) inv[s] = 1.0f / block_sum(psum[s], s_redf);

        // AV: each V row read once, used for QT queries
        const int d = tid & (HID - 1);
        const int half = tid >> 7;
        float acc[QT] = {0.f, 0.f, 0.f, 0.f};
        for (int j = half; j < n_max; j += 2) {
            float vv = vbase[(size_t)j * HID + d];
            #pragma unroll
            for (int s = 0; s < QT; s++)
                acc[s] = fmaf(s_sc[s * T_SRC + j], vv, acc[s]);
        }
        #pragma unroll
        for (int s = 0; s < QT; s++) {
            s_buf[tid] = acc[s];
            __syncthreads();
            if (tid < HID)
                out[((size_t)h * T_DST + qi0 + s) * HID + tid] =
                    (s_buf[tid] + s_buf[tid + HID]) * inv[s];
            __syncthreads();
        }
    } else {
        // ================= sparse: exact top-128 via 4-level radix select =================
        const int bound = ((n_max + NT - 1) / NT) * NT;  // uniform trip count for match_any

        #pragma unroll 1
        for (int s = 0; s < QT; s++) {
            const float* sc = s_sc + s * T_SRC;
            unsigned prefix = 0, ngt = 0;

            #pragma unroll 1
            for (int level = 3; level >= 0; level--) {
                // clear histogram (257 bins; bin 256 = "not a candidate")
                if (tid < 257) s_hist[tid] = 0u;
                if (tid >= 257 && tid < 258) {}  // no-op
                __syncthreads();

                const unsigned shift = level * 8;
                const unsigned pmask = (level == 3) ? 0u : (0xFFFFFFFFu << (shift + 8));

                for (int j = tid; j < bound; j += NT) {
                    unsigned bin = 256u;
                    if (j < n_max) {
                        unsigned key = fkey(sc[j]);
                        if ((key & pmask) == prefix) bin = (key >> shift) & 0xFFu;
                    }
                    unsigned peers = __match_any_sync(0xFFFFFFFFu, bin);
                    if ((__ffs(peers) - 1) == (tid & 31))
                        atomicAdd(&s_hist[bin], (unsigned)__popc(peers));
                }
                __syncthreads();

                // warp 0: suffix-scan 256 bins from the top, find the K-th boundary bin
                if (tid < 32) {
                    unsigned g = 0;
                    #pragma unroll
                    for (int b = 0; b < 8; b++) g += s_hist[tid * 8 + b];
                    unsigned run = g;
                    #pragma unroll
                    for (int o = 1; o < 32; o <<= 1) {
                        unsigned u = __shfl_down_sync(0xFFFFFFFFu, run, o);
                        if (tid + o < 32) run += u;
                    }
                    unsigned S = run - g;  // count in groups strictly above mine
                    if (ngt + run >= KTOP && ngt + S < KTOP) {
                        unsigned acc2 = ngt + S;
                        #pragma unroll 1
                        for (int b = 7; b >= 0; b--) {
                            unsigned c = s_hist[tid * 8 + b];
                            if (acc2 + c >= KTOP) {
                                s_cnt[0] = prefix | ((unsigned)(tid * 8 + b) << shift);
                                s_cnt[1] = acc2;
                                break;
                            }
                            acc2 += c;
                        }
                    }
                }
                __syncthreads();
                prefix = s_cnt[0];
                ngt = s_cnt[1];
                __syncthreads();
            }

            const unsigned t_key = prefix;  // exact 128th-largest key; ngt = count(> t_key)

            if (tid == 0) { s_cnt[2] = 0u; s_cnt[3] = 0u; }
            __syncthreads();
            for (int j = tid; j < n_max; j += NT) {
                unsigned key = fkey(sc[j]);
                if (key > t_key) {
                    unsigned p = atomicAdd(&s_cnt[2], 1u);
                    s_idx[s * KTOP + p] = j;
                } else if (key == t_key) {
                    unsigned p = atomicAdd(&s_cnt[3], 1u);
                    if (p < KTOP) s_eq[p] = j;
                }
            }
            __syncthreads();
            const int neq = (int)s_cnt[3];
            const int need = KTOP - (int)ngt;  // 1 <= need <= neq

            if (need < neq && tid == 0) {
                // rare tie case: pick `need` smallest indices (jax top_k tie order)
                int c = (neq < KTOP) ? neq : KTOP;
                for (int a = 0; a < need; a++) {
                    int mb = a;
                    for (int b = a + 1; b < c; b++)
                        if (s_eq[b] < s_eq[mb]) mb = b;
                    int t2 = s_eq[a]; s_eq[a] = s_eq[mb]; s_eq[mb] = t2;
                }
            }
            __syncthreads();
            for (int a = tid; a < need; a += NT) s_idx[s * KTOP + (int)ngt + a] = s_eq[a];
            __syncthreads();

            // softmax weights over selected 128 (row max is in the set)
            float e = 0.0f;
            if (tid < KTOP) {
                e = __expf(sc[s_idx[s * KTOP + tid]] - m[s]);
                s_w[s * KTOP + tid] = e;
            }
            float tot = block_sum(e, s_redf);
            inv[s] = 1.0f / tot;
        }

        // AV over gathered rows
        const int d = tid & (HID - 1);
        const int half = tid >> 7;
        float acc[QT] = {0.f, 0.f, 0.f, 0.f};
        for (int a = half; a < KTOP; a += 2) {
            #pragma unroll
            for (int s = 0; s < QT; s++) {
                int j = s_idx[s * KTOP + a];
                acc[s] = fmaf(s_w[s * KTOP + a], vbase[(size_t)j * HID + d], acc[s]);
            }
        }
        #pragma unroll
        for (int s = 0; s < QT; s++) {
            s_buf[tid] = acc[s];
            __syncthreads();
            if (tid < HID)
                out[((size_t)h * T_DST + qi0 + s) * HID + tid] =
                    (s_buf[tid] + s_buf[tid + HID]) * inv[s];
            __syncthreads();
        }
    }
}

extern "C" void kernel_launch(void* const* d_in, const int* in_sizes, int n_in,
                              void* d_out, int out_size) {
    const float* q = (const float*)d_in[0];
    const float* k = (const float*)d_in[1];
    const float* v = (const float*)d_in[2];
    float* out = (float*)d_out;

    cudaFuncSetAttribute(tree_attn_tiled,
                         cudaFuncAttributeMaxDynamicSharedMemorySize, DYN_BYTES);

    dim3 grid(NTILES, NHEADS);
    tree_attn_tiled<<<grid, NT, DYN_BYTES>>>(q, k, v, out);
}